// round 11
// baseline (speedup 1.0000x reference)
#include <cuda_runtime.h>

#define DIM     33
#define DIM2    (DIM*DIM)            // 1089
#define CELLS   (DIM*DIM*DIM)        // 35937
#define PLANE   (1080u*1920u)        // 2073600 pixels per channel plane
#define NIMG    16
#define GPI8    (PLANE/8u)           // 259200 groups of 8 pixels per image

// One 32B-aligned entry per cell (b,g,r) holds ALL 8 corners x 3 channels at
// 10-bit fixed point: word k (k = cb*4+cg*2+cr) = R | G<<10 | B<<20.
// A pixel reads its entry with ONE 256-bit load (ld.global.nc.v8.b32).
struct __align__(32) Cell2 { uint4 lo, hi; };
__device__ Cell2 g_cell2[CELLS];     // 1.15 MB, L2-resident

__global__ void repack_kernel(const float* __restrict__ lut) {
    int i = blockIdx.x * blockDim.x + threadIdx.x;
    if (i >= CELLS) return;
    int b = i / DIM2;
    int rem = i - b * DIM2;
    int g = rem / DIM;
    int r = rem - g * DIM;
    int rr[2] = { r, min(r + 1, DIM - 1) };
    int gg[2] = { g, min(g + 1, DIM - 1) };
    int bb[2] = { b, min(b + 1, DIM - 1) };

    unsigned w[8];
    #pragma unroll
    for (int cb = 0; cb < 2; cb++)
      #pragma unroll
      for (int cg = 0; cg < 2; cg++)
        #pragma unroll
        for (int cr = 0; cr < 2; cr++) {
            int idx = bb[cb] * DIM2 + gg[cg] * DIM + rr[cr];
            unsigned R = (unsigned)rintf(lut[idx]             * 1023.0f);
            unsigned G = (unsigned)rintf(lut[idx + CELLS]     * 1023.0f);
            unsigned B = (unsigned)rintf(lut[idx + 2 * CELLS] * 1023.0f);
            w[cb * 4 + cg * 2 + cr] = R | (G << 10) | (B << 20);
        }
    Cell2 c;
    c.lo = make_uint4(w[0], w[1], w[2], w[3]);
    c.hi = make_uint4(w[4], w[5], w[6], w[7]);
    g_cell2[i] = c;
}

struct F3 { float x, y, z; };

#define MAGIC 0x4B000000u            // as_float(MAGIC | q) = 2^23 + q, exact
#define BIGC  8388608.0f             // 2^23

// Trilinear lerp over 8 biased corners f[k] = 2^23 + q_k.
// Diffs (f1-f0 = q1-q0) and addends (f0 - 2^23 = q0) are EXACT.
__device__ __forceinline__ float trilerp(const float* f,
                                         float rd, float gd, float bd) {
    float c00 = fmaf(rd, f[1] - f[0], f[0] - BIGC);
    float c10 = fmaf(rd, f[3] - f[2], f[2] - BIGC);
    float c01 = fmaf(rd, f[5] - f[4], f[4] - BIGC);
    float c11 = fmaf(rd, f[7] - f[6], f[6] - BIGC);
    float c0  = fmaf(gd, c10 - c00, c00);
    float c1  = fmaf(gd, c11 - c01, c01);
    return fmaf(bd, c1 - c0, c0);
}

__device__ __forceinline__ F3 sample_lut(float r, float g, float b) {
    const float inv = 32.0f / 1.000001f;   // 1/binsize
    float tr = r * inv, tg = g * inv, tb = b * inv;

    int ir = (int)tr, ig = (int)tg, ib = (int)tb;    // floor (x >= 0)
    float rd = tr - (float)ir;
    float gd = tg - (float)ig;
    float bd = tb - (float)ib;
    ir = min(ir, DIM - 2);      // x >= 0 -> no lower clamp needed
    ig = min(ig, DIM - 2);
    ib = min(ib, DIM - 2);

    int i00 = ib * DIM2 + ig * DIM + ir;

    // Single 256-bit non-coherent load of the whole cell (sm_10x).
    unsigned w[8];
    {
        const void* p = (const void*)&g_cell2[i00];
        asm volatile("ld.global.nc.v8.b32 {%0,%1,%2,%3,%4,%5,%6,%7}, [%8];"
                     : "=r"(w[0]), "=r"(w[1]), "=r"(w[2]), "=r"(w[3]),
                       "=r"(w[4]), "=r"(w[5]), "=r"(w[6]), "=r"(w[7])
                     : "l"(p));
    }

    float fR[8], fG[8], fB[8];
    #pragma unroll
    for (int k = 0; k < 8; k++) {
        fR[k] = __uint_as_float(( w[k]        & 1023u) | MAGIC);  // LOP3
        fG[k] = __uint_as_float(((w[k] >> 10) & 1023u) | MAGIC);  // SHF+LOP3
        fB[k] = __uint_as_float( (w[k] >> 20)          | MAGIC);  // SHF+LOP
    }

    const float s = 1.0f / 1023.0f;
    F3 o;
    o.x = trilerp(fR, rd, gd, bd) * s;
    o.y = trilerp(fG, rd, gd, bd) * s;
    o.z = trilerp(fB, rd, gd, bd) * s;
    return o;
}

__global__ __launch_bounds__(256) void lut3d_kernel(
    const float* __restrict__ x, float* __restrict__ out)
{
    unsigned tid = blockIdx.x * blockDim.x + threadIdx.x; // one thread = 8 px
    unsigned n  = tid / GPI8;
    unsigned p8 = (tid - n * GPI8) * 8u;

    // 32-bit offsets: total elements 99.5M < 2^31
    unsigned base = n * 3u * PLANE + p8;

    // 8 consecutive pixels = two float4 groups per plane
    float4 rv0 = __ldcs((const float4*)(x + base));
    float4 rv1 = __ldcs((const float4*)(x + base + 4u));
    float4 gv0 = __ldcs((const float4*)(x + base + PLANE));
    float4 gv1 = __ldcs((const float4*)(x + base + PLANE + 4u));
    float4 bv0 = __ldcs((const float4*)(x + base + 2u * PLANE));
    float4 bv1 = __ldcs((const float4*)(x + base + 2u * PLANE + 4u));

    F3 o0 = sample_lut(rv0.x, gv0.x, bv0.x);
    F3 o1 = sample_lut(rv0.y, gv0.y, bv0.y);
    F3 o2 = sample_lut(rv0.z, gv0.z, bv0.z);
    F3 o3 = sample_lut(rv0.w, gv0.w, bv0.w);
    F3 o4 = sample_lut(rv1.x, gv1.x, bv1.x);
    F3 o5 = sample_lut(rv1.y, gv1.y, bv1.y);
    F3 o6 = sample_lut(rv1.z, gv1.z, bv1.z);
    F3 o7 = sample_lut(rv1.w, gv1.w, bv1.w);

    __stcs((float4*)(out + base),                   make_float4(o0.x, o1.x, o2.x, o3.x));
    __stcs((float4*)(out + base + 4u),              make_float4(o4.x, o5.x, o6.x, o7.x));
    __stcs((float4*)(out + base + PLANE),           make_float4(o0.y, o1.y, o2.y, o3.y));
    __stcs((float4*)(out + base + PLANE + 4u),      make_float4(o4.y, o5.y, o6.y, o7.y));
    __stcs((float4*)(out + base + 2u * PLANE),      make_float4(o0.z, o1.z, o2.z, o3.z));
    __stcs((float4*)(out + base + 2u * PLANE + 4u), make_float4(o4.z, o5.z, o6.z, o7.z));
}

extern "C" void kernel_launch(void* const* d_in, const int* in_sizes, int n_in,
                              void* d_out, int out_size) {
    const float* lut = (const float*)d_in[0];   // (3, 33, 33, 33) fp32
    const float* x   = (const float*)d_in[1];   // (16, 3, 1080, 1920) fp32
    float* out = (float*)d_out;                 // (16, 3, 1080, 1920) fp32

    repack_kernel<<<(CELLS + 255) / 256, 256>>>(lut);

    unsigned total_threads = NIMG * GPI8;       // 4,147,200 threads
    lut3d_kernel<<<total_threads / 256, 256>>>(x, out);
}

// round 12
// speedup vs baseline: 1.0838x; 1.0838x over previous
#include <cuda_runtime.h>

#define DIM     33
#define DIM2    (DIM*DIM)            // 1089
#define CELLS   (DIM*DIM*DIM)        // 35937
#define PLANE   (1080u*1920u)        // 2073600 pixels per channel plane
#define NIMG    16
#define GPI     (PLANE/4u)           // 518400 groups of 4 pixels per image

// One 32B-aligned entry per cell (b,g,r) holds ALL 8 corners x 3 channels at
// 10-bit fixed point: word k (k = cb*4+cg*2+cr) = R | G<<10 | B<<20.
// A pixel reads its entry with ONE 256-bit load (ld.global.nc.v8.b32).
struct __align__(32) Cell2 { uint4 lo, hi; };
__device__ Cell2 g_cell2[CELLS];     // 1.15 MB, L2-resident

__global__ void repack_kernel(const float* __restrict__ lut) {
    int i = blockIdx.x * blockDim.x + threadIdx.x;
    if (i >= CELLS) return;
    int b = i / DIM2;
    int rem = i - b * DIM2;
    int g = rem / DIM;
    int r = rem - g * DIM;
    int rr[2] = { r, min(r + 1, DIM - 1) };
    int gg[2] = { g, min(g + 1, DIM - 1) };
    int bb[2] = { b, min(b + 1, DIM - 1) };

    unsigned w[8];
    #pragma unroll
    for (int cb = 0; cb < 2; cb++)
      #pragma unroll
      for (int cg = 0; cg < 2; cg++)
        #pragma unroll
        for (int cr = 0; cr < 2; cr++) {
            int idx = bb[cb] * DIM2 + gg[cg] * DIM + rr[cr];
            unsigned R = (unsigned)rintf(lut[idx]             * 1023.0f);
            unsigned G = (unsigned)rintf(lut[idx + CELLS]     * 1023.0f);
            unsigned B = (unsigned)rintf(lut[idx + 2 * CELLS] * 1023.0f);
            w[cb * 4 + cg * 2 + cr] = R | (G << 10) | (B << 20);
        }
    Cell2 c;
    c.lo = make_uint4(w[0], w[1], w[2], w[3]);
    c.hi = make_uint4(w[4], w[5], w[6], w[7]);
    g_cell2[i] = c;
}

struct F3 { float x, y, z; };

#define MAGIC 0x4B000000u            // as_float(MAGIC | q) = 2^23 + q, exact
#define BIGC  8388608.0f             // 2^23

// 256-bit cell fetch (sm_10x). asm volatile pins issue order -> explicit
// software pipeline; exactly two windows (wA/wB) are ever live.
#define LOADCELL(W, idx)                                                   \
    asm volatile("ld.global.nc.v8.b32 {%0,%1,%2,%3,%4,%5,%6,%7}, [%8];"    \
                 : "=r"(W[0]), "=r"(W[1]), "=r"(W[2]), "=r"(W[3]),         \
                   "=r"(W[4]), "=r"(W[5]), "=r"(W[6]), "=r"(W[7])          \
                 : "l"((const void*)&g_cell2[idx]))

// Trilinear lerp over 8 biased corners f[k] = 2^23 + q_k.
// Diffs (f1-f0 = q1-q0) and addends (f0 - 2^23 = q0) are EXACT.
__device__ __forceinline__ float trilerp(const float* f,
                                         float rd, float gd, float bd) {
    float c00 = fmaf(rd, f[1] - f[0], f[0] - BIGC);
    float c10 = fmaf(rd, f[3] - f[2], f[2] - BIGC);
    float c01 = fmaf(rd, f[5] - f[4], f[4] - BIGC);
    float c11 = fmaf(rd, f[7] - f[6], f[6] - BIGC);
    float c0  = fmaf(gd, c10 - c00, c00);
    float c1  = fmaf(gd, c11 - c01, c01);
    return fmaf(bd, c1 - c0, c0);
}

// Decode a loaded cell window and trilerp all 3 channels.
__device__ __forceinline__ F3 shade(const unsigned* w,
                                    float rd, float gd, float bd) {
    float fR[8], fG[8], fB[8];
    #pragma unroll
    for (int k = 0; k < 8; k++) {
        fR[k] = __uint_as_float(( w[k]        & 1023u) | MAGIC);  // LOP3
        fG[k] = __uint_as_float(((w[k] >> 10) & 1023u) | MAGIC);  // SHF+LOP3
        fB[k] = __uint_as_float( (w[k] >> 20)          | MAGIC);  // SHF+LOP
    }
    const float s = 1.0f / 1023.0f;
    F3 o;
    o.x = trilerp(fR, rd, gd, bd) * s;
    o.y = trilerp(fG, rd, gd, bd) * s;
    o.z = trilerp(fB, rd, gd, bd) * s;
    return o;
}

// Index + fracs. x in [0,1) -> t in [0,32) -> floor(t) in [0,31]: NO clamps.
__device__ __forceinline__ int cell_index(float r, float g, float b,
                                          float& rd, float& gd, float& bd) {
    const float inv = 32.0f / 1.000001f;   // 1/binsize
    float tr = r * inv, tg = g * inv, tb = b * inv;
    int ir = (int)tr, ig = (int)tg, ib = (int)tb;    // floor; already in [0,31]
    rd = tr - (float)ir;
    gd = tg - (float)ig;
    bd = tb - (float)ib;
    return ib * DIM2 + ig * DIM + ir;
}

__global__ __launch_bounds__(256, 2) void lut3d_kernel(
    const float* __restrict__ x, float* __restrict__ out)
{
    unsigned tid = blockIdx.x * blockDim.x + threadIdx.x; // one thread = 4 px
    unsigned n  = tid / GPI;
    unsigned p4 = (tid - n * GPI) * 4u;

    unsigned base = n * 3u * PLANE + p4;    // 32-bit offsets (99.5M elems < 2^31)
    float4 rv = __ldcs((const float4*)(x + base));
    float4 gv = __ldcs((const float4*)(x + base + PLANE));
    float4 bv = __ldcs((const float4*)(x + base + 2u * PLANE));

    float rd0, gd0, bd0, rd1, gd1, bd1, rd2, gd2, bd2, rd3, gd3, bd3;
    int i0 = cell_index(rv.x, gv.x, bv.x, rd0, gd0, bd0);
    int i1 = cell_index(rv.y, gv.y, bv.y, rd1, gd1, bd1);
    int i2 = cell_index(rv.z, gv.z, bv.z, rd2, gd2, bd2);
    int i3 = cell_index(rv.w, gv.w, bv.w, rd3, gd3, bd3);

    // Rotating double-buffer: 2 cell fetches in flight, each load issued one
    // shade() ahead of its use.
    unsigned wA[8], wB[8];
    LOADCELL(wA, i0);
    LOADCELL(wB, i1);
    F3 o0 = shade(wA, rd0, gd0, bd0);
    LOADCELL(wA, i2);
    F3 o1 = shade(wB, rd1, gd1, bd1);
    LOADCELL(wB, i3);
    F3 o2 = shade(wA, rd2, gd2, bd2);
    F3 o3 = shade(wB, rd3, gd3, bd3);

    __stcs((float4*)(out + base),              make_float4(o0.x, o1.x, o2.x, o3.x));
    __stcs((float4*)(out + base + PLANE),      make_float4(o0.y, o1.y, o2.y, o3.y));
    __stcs((float4*)(out + base + 2u * PLANE), make_float4(o0.z, o1.z, o2.z, o3.z));
}

extern "C" void kernel_launch(void* const* d_in, const int* in_sizes, int n_in,
                              void* d_out, int out_size) {
    const float* lut = (const float*)d_in[0];   // (3, 33, 33, 33) fp32
    const float* x   = (const float*)d_in[1];   // (16, 3, 1080, 1920) fp32
    float* out = (float*)d_out;                 // (16, 3, 1080, 1920) fp32

    repack_kernel<<<(CELLS + 255) / 256, 256>>>(lut);

    unsigned total_groups = NIMG * GPI;         // 8,294,400 threads
    lut3d_kernel<<<total_groups / 256, 256>>>(x, out);
}

// round 13
// speedup vs baseline: 1.2289x; 1.1338x over previous
#include <cuda_runtime.h>

#define DIM     33
#define DIM2    (DIM*DIM)            // 1089
#define CELLS   (DIM*DIM*DIM)        // 35937
#define PLANE   (1080u*1920u)        // 2073600 pixels per channel plane
#define NIMG    16
#define GPI     (PLANE/4u)           // 518400 groups of 4 pixels per image

// One 32B-aligned entry per cell (b,g,r) holds ALL 8 corners x 3 channels at
// 10-bit fixed point: word k (k = cb*4+cg*2+cr) = R | G<<10 | B<<20.
// A pixel reads its entry with ONE 256-bit load (ld.global.nc.v8.b32).
struct __align__(32) Cell2 { uint4 lo, hi; };
__device__ Cell2 g_cell2[CELLS];     // 1.15 MB, L2-resident

__global__ void repack_kernel(const float* __restrict__ lut) {
    int i = blockIdx.x * blockDim.x + threadIdx.x;
    if (i >= CELLS) return;
    int b = i / DIM2;
    int rem = i - b * DIM2;
    int g = rem / DIM;
    int r = rem - g * DIM;
    int rr[2] = { r, min(r + 1, DIM - 1) };
    int gg[2] = { g, min(g + 1, DIM - 1) };
    int bb[2] = { b, min(b + 1, DIM - 1) };

    unsigned w[8];
    #pragma unroll
    for (int cb = 0; cb < 2; cb++)
      #pragma unroll
      for (int cg = 0; cg < 2; cg++)
        #pragma unroll
        for (int cr = 0; cr < 2; cr++) {
            int idx = bb[cb] * DIM2 + gg[cg] * DIM + rr[cr];
            unsigned R = (unsigned)rintf(lut[idx]             * 1023.0f);
            unsigned G = (unsigned)rintf(lut[idx + CELLS]     * 1023.0f);
            unsigned B = (unsigned)rintf(lut[idx + 2 * CELLS] * 1023.0f);
            w[cb * 4 + cg * 2 + cr] = R | (G << 10) | (B << 20);
        }
    Cell2 c;
    c.lo = make_uint4(w[0], w[1], w[2], w[3]);
    c.hi = make_uint4(w[4], w[5], w[6], w[7]);
    g_cell2[i] = c;
}

struct F3 { float x, y, z; };

#define MAGIC 0x4B000000u            // as_float(MAGIC | q) = 2^23 + q, exact
#define BIGC  8388608.0f             // 2^23

// Trilinear lerp over 8 biased corners f[k] = 2^23 + q_k.
// Diffs (f1-f0 = q1-q0) and addends (f0 - 2^23 = q0) are EXACT.
__device__ __forceinline__ float trilerp(const float* f,
                                         float rd, float gd, float bd) {
    float c00 = fmaf(rd, f[1] - f[0], f[0] - BIGC);
    float c10 = fmaf(rd, f[3] - f[2], f[2] - BIGC);
    float c01 = fmaf(rd, f[5] - f[4], f[4] - BIGC);
    float c11 = fmaf(rd, f[7] - f[6], f[6] - BIGC);
    float c0  = fmaf(gd, c10 - c00, c00);
    float c1  = fmaf(gd, c11 - c01, c01);
    return fmaf(bd, c1 - c0, c0);
}

__device__ __forceinline__ F3 sample_lut(float r, float g, float b) {
    const float inv = 32.0f / 1.000001f;   // 1/binsize
    float tr = r * inv, tg = g * inv, tb = b * inv;

    // x in [0,1) -> t in [0,32) -> floor(t) in [0,31] = [0, DIM-2]: NO clamps.
    int ir = (int)tr, ig = (int)tg, ib = (int)tb;
    float rd = tr - (float)ir;
    float gd = tg - (float)ig;
    float bd = tb - (float)ib;

    int i00 = ib * DIM2 + ig * DIM + ir;

    // Single 256-bit non-coherent load of the whole cell (sm_10x),
    // compiler-scheduled (r10 form: proven fastest, never spills).
    unsigned w[8];
    {
        const void* p = (const void*)&g_cell2[i00];
        asm volatile("ld.global.nc.v8.b32 {%0,%1,%2,%3,%4,%5,%6,%7}, [%8];"
                     : "=r"(w[0]), "=r"(w[1]), "=r"(w[2]), "=r"(w[3]),
                       "=r"(w[4]), "=r"(w[5]), "=r"(w[6]), "=r"(w[7])
                     : "l"(p));
    }

    float fR[8], fG[8], fB[8];
    #pragma unroll
    for (int k = 0; k < 8; k++) {
        fR[k] = __uint_as_float(( w[k]        & 1023u) | MAGIC);  // LOP3
        fG[k] = __uint_as_float(((w[k] >> 10) & 1023u) | MAGIC);  // SHF+LOP3
        fB[k] = __uint_as_float( (w[k] >> 20)          | MAGIC);  // SHF+LOP
    }

    const float s = 1.0f / 1023.0f;
    F3 o;
    o.x = trilerp(fR, rd, gd, bd) * s;
    o.y = trilerp(fG, rd, gd, bd) * s;
    o.z = trilerp(fB, rd, gd, bd) * s;
    return o;
}

__global__ __launch_bounds__(256) void lut3d_kernel(
    const float* __restrict__ x, float* __restrict__ out)
{
    unsigned tid = blockIdx.x * blockDim.x + threadIdx.x; // one thread = 4 px
    unsigned n  = tid / GPI;
    unsigned p4 = (tid - n * GPI) * 4u;

    // 32-bit offsets: total elements 99.5M < 2^31 -> no 64-bit index math
    unsigned base = n * 3u * PLANE + p4;
    float4 rv = __ldcs((const float4*)(x + base));
    float4 gv = __ldcs((const float4*)(x + base + PLANE));
    float4 bv = __ldcs((const float4*)(x + base + 2u * PLANE));

    F3 o0 = sample_lut(rv.x, gv.x, bv.x);
    F3 o1 = sample_lut(rv.y, gv.y, bv.y);
    F3 o2 = sample_lut(rv.z, gv.z, bv.z);
    F3 o3 = sample_lut(rv.w, gv.w, bv.w);

    __stcs((float4*)(out + base),              make_float4(o0.x, o1.x, o2.x, o3.x));
    __stcs((float4*)(out + base + PLANE),      make_float4(o0.y, o1.y, o2.y, o3.y));
    __stcs((float4*)(out + base + 2u * PLANE), make_float4(o0.z, o1.z, o2.z, o3.z));
}

extern "C" void kernel_launch(void* const* d_in, const int* in_sizes, int n_in,
                              void* d_out, int out_size) {
    const float* lut = (const float*)d_in[0];   // (3, 33, 33, 33) fp32
    const float* x   = (const float*)d_in[1];   // (16, 3, 1080, 1920) fp32
    float* out = (float*)d_out;                 // (16, 3, 1080, 1920) fp32

    repack_kernel<<<(CELLS + 255) / 256, 256>>>(lut);

    unsigned total_groups = NIMG * GPI;         // 8,294,400 threads
    lut3d_kernel<<<total_groups / 256, 256>>>(x, out);
}

// round 14
// speedup vs baseline: 1.2867x; 1.0471x over previous
#include <cuda_runtime.h>

#define DIM     33
#define DIM2    (DIM*DIM)            // 1089
#define CELLS   (DIM*DIM*DIM)        // 35937
#define PLANE   (1080u*1920u)        // 2073600 pixels per channel plane
#define NIMG    16
#define GPI     (PLANE/4u)           // 518400 groups of 4 pixels per image

// One 32B-aligned entry per cell (b,g,r) holds ALL 8 corners x 3 channels at
// 10-bit fixed point: word k (k = cb*4+cg*2+cr) = R | G<<10 | B<<20.
// A pixel reads its entry with ONE 256-bit load (ld.global.nc.v8.b32).
struct __align__(32) Cell2 { uint4 lo, hi; };
__device__ Cell2 g_cell2[CELLS];     // 1.15 MB, L2-resident

__global__ void repack_kernel(const float* __restrict__ lut) {
    int i = blockIdx.x * blockDim.x + threadIdx.x;
    if (i >= CELLS) return;
    int b = i / DIM2;
    int rem = i - b * DIM2;
    int g = rem / DIM;
    int r = rem - g * DIM;
    int rr[2] = { r, min(r + 1, DIM - 1) };
    int gg[2] = { g, min(g + 1, DIM - 1) };
    int bb[2] = { b, min(b + 1, DIM - 1) };

    unsigned w[8];
    #pragma unroll
    for (int cb = 0; cb < 2; cb++)
      #pragma unroll
      for (int cg = 0; cg < 2; cg++)
        #pragma unroll
        for (int cr = 0; cr < 2; cr++) {
            int idx = bb[cb] * DIM2 + gg[cg] * DIM + rr[cr];
            unsigned R = (unsigned)rintf(lut[idx]             * 1023.0f);
            unsigned G = (unsigned)rintf(lut[idx + CELLS]     * 1023.0f);
            unsigned B = (unsigned)rintf(lut[idx + 2 * CELLS] * 1023.0f);
            w[cb * 4 + cg * 2 + cr] = R | (G << 10) | (B << 20);
        }
    Cell2 c;
    c.lo = make_uint4(w[0], w[1], w[2], w[3]);
    c.hi = make_uint4(w[4], w[5], w[6], w[7]);
    g_cell2[i] = c;
}

struct F3 { float x, y, z; };

#define MAGIC 0x4B000000u            // as_float(MAGIC | q) = 2^23 + q, exact
#define BIGC  8388608.0f             // 2^23

// Trilinear lerp over 8 biased corners f[k] = 2^23 + q_k.
// Diffs (f1-f0 = q1-q0) and addends (f0 - 2^23 = q0) are EXACT.
__device__ __forceinline__ float trilerp(const float* f,
                                         float rd, float gd, float bd) {
    float c00 = fmaf(rd, f[1] - f[0], f[0] - BIGC);
    float c10 = fmaf(rd, f[3] - f[2], f[2] - BIGC);
    float c01 = fmaf(rd, f[5] - f[4], f[4] - BIGC);
    float c11 = fmaf(rd, f[7] - f[6], f[6] - BIGC);
    float c0  = fmaf(gd, c10 - c00, c00);
    float c1  = fmaf(gd, c11 - c01, c01);
    return fmaf(bd, c1 - c0, c0);
}

__device__ __forceinline__ F3 sample_lut(float r, float g, float b) {
    const float inv = 32.0f / 1.000001f;   // 1/binsize
    float tr = r * inv, tg = g * inv, tb = b * inv;

    int ir = (int)tr, ig = (int)tg, ib = (int)tb;    // floor (x >= 0)
    float rd = tr - (float)ir;
    float gd = tg - (float)ig;
    float bd = tb - (float)ib;
    ir = min(ir, DIM - 2);      // x >= 0 -> no lower clamp needed
    ig = min(ig, DIM - 2);
    ib = min(ib, DIM - 2);

    int i00 = ib * DIM2 + ig * DIM + ir;

    // Single 256-bit non-coherent load of the whole cell (sm_10x).
    unsigned w[8];
    {
        const void* p = (const void*)&g_cell2[i00];
        asm volatile("ld.global.nc.v8.b32 {%0,%1,%2,%3,%4,%5,%6,%7}, [%8];"
                     : "=r"(w[0]), "=r"(w[1]), "=r"(w[2]), "=r"(w[3]),
                       "=r"(w[4]), "=r"(w[5]), "=r"(w[6]), "=r"(w[7])
                     : "l"(p));
    }

    float fR[8], fG[8], fB[8];
    #pragma unroll
    for (int k = 0; k < 8; k++) {
        fR[k] = __uint_as_float(( w[k]        & 1023u) | MAGIC);  // LOP3
        fG[k] = __uint_as_float(((w[k] >> 10) & 1023u) | MAGIC);  // SHF+LOP3
        fB[k] = __uint_as_float( (w[k] >> 20)          | MAGIC);  // SHF+LOP
    }

    const float s = 1.0f / 1023.0f;
    F3 o;
    o.x = trilerp(fR, rd, gd, bd) * s;
    o.y = trilerp(fG, rd, gd, bd) * s;
    o.z = trilerp(fB, rd, gd, bd) * s;
    return o;
}

__global__ __launch_bounds__(256) void lut3d_kernel(
    const float* __restrict__ x, float* __restrict__ out)
{
    unsigned tid = blockIdx.x * blockDim.x + threadIdx.x; // one thread = 4 px
    unsigned n  = tid / GPI;
    unsigned p4 = (tid - n * GPI) * 4u;

    // 32-bit offsets: total elements 99.5M < 2^31 -> no 64-bit index math
    unsigned base = n * 3u * PLANE + p4;
    const float4* xr = (const float4*)(x + base);
    const float4* xg = (const float4*)(x + base + PLANE);
    const float4* xb = (const float4*)(x + base + 2u * PLANE);
    float4 rv = __ldcs(xr);
    float4 gv = __ldcs(xg);
    float4 bv = __ldcs(xb);

    F3 o0 = sample_lut(rv.x, gv.x, bv.x);
    F3 o1 = sample_lut(rv.y, gv.y, bv.y);
    F3 o2 = sample_lut(rv.z, gv.z, bv.z);
    F3 o3 = sample_lut(rv.w, gv.w, bv.w);

    __stcs((float4*)(out + base),              make_float4(o0.x, o1.x, o2.x, o3.x));
    __stcs((float4*)(out + base + PLANE),      make_float4(o0.y, o1.y, o2.y, o3.y));
    __stcs((float4*)(out + base + 2u * PLANE), make_float4(o0.z, o1.z, o2.z, o3.z));
}

extern "C" void kernel_launch(void* const* d_in, const int* in_sizes, int n_in,
                              void* d_out, int out_size) {
    const float* lut = (const float*)d_in[0];   // (3, 33, 33, 33) fp32
    const float* x   = (const float*)d_in[1];   // (16, 3, 1080, 1920) fp32
    float* out = (float*)d_out;                 // (16, 3, 1080, 1920) fp32

    repack_kernel<<<(CELLS + 255) / 256, 256>>>(lut);

    unsigned total_groups = NIMG * GPI;         // 8,294,400 threads
    lut3d_kernel<<<total_groups / 256, 256>>>(x, out);
}